// round 9
// baseline (speedup 1.0000x reference)
#include <cuda_runtime.h>
#include <cstdint>

struct State { double acc; unsigned long long count; };
__device__ State g_state;

static constexpr int BLOCKS  = 444;    // 3 blocks/SM on 148 SMs, persistent
static constexpr int THREADS = 256;    // 8 warps/block
static constexpr int WARPS_TOTAL = BLOCKS * (THREADS / 32);

// Explicit double-buffer, unroll-by-2: identical distance-1 pipeline to the
// R6 winner but with zero snapshot copies. Per half-iteration: issue the
// next row's 8 float4 loads into the dead buffer, then consume the pending
// buffer (FMA pass + in-pass label extraction + shuffle tail).
struct RowBuf { float4 v[8]; int lab; };

__device__ __forceinline__ void load_row(RowBuf& b,
                                         const float* __restrict__ logits,
                                         const int* __restrict__ labels,
                                         int row, int C, int lane) {
    const float4* __restrict__ row4 =
        reinterpret_cast<const float4*>(logits + (size_t)row * (size_t)C);
    b.lab = __ldg(labels + row);
    #pragma unroll
    for (int k = 0; k < 7; k++)
        b.v[k] = __ldcs(row4 + lane + 32 * k);
    b.v[7] = make_float4(0.f, 0.f, 0.f, 0.f);
    if (lane < 26)
        b.v[7] = __ldcs(row4 + lane + 224);
}

__device__ __forceinline__ void consume_row(const RowBuf& b, int lane,
                                            double& local) {
    const int j4   = b.lab >> 2;          // float4 index in row [0,250)
    const int comp = b.lab & 3;
    const int lane_owner = j4 & 31;

    float s0 = 0.f, s1 = 0.f, s2 = 0.f, s3 = 0.f;
    float dot_l = 0.0f;
    #pragma unroll
    for (int k = 0; k < 8; k++) {
        if (j4 == lane + 32 * k) {
            dot_l = (comp == 0) ? b.v[k].x :
                    (comp == 1) ? b.v[k].y :
                    (comp == 2) ? b.v[k].z : b.v[k].w;
        }
        s0 = fmaf(b.v[k].x, b.v[k].x, s0);
        s1 = fmaf(b.v[k].y, b.v[k].y, s1);
        s2 = fmaf(b.v[k].z, b.v[k].z, s2);
        s3 = fmaf(b.v[k].w, b.v[k].w, s3);
    }
    float s = (s0 + s1) + (s2 + s3);
    #pragma unroll
    for (int o = 16; o > 0; o >>= 1)
        s += __shfl_xor_sync(0xFFFFFFFFu, s, o);
    const float dot = __shfl_sync(0xFFFFFFFFu, dot_l, lane_owner);

    if (lane == 0) {
        const float cosv = dot / fmaxf(sqrtf(s), 1e-8f);
        local += 1.0 - (double)cosv;
    }
}

__global__ __launch_bounds__(THREADS, 3)
void cosine_loss_kernel(const float* __restrict__ logits,
                        const int* __restrict__ labels,
                        int N, int C, float* __restrict__ out, double inv_n) {
    const int lane  = threadIdx.x & 31;
    const int warp_in_block = threadIdx.x >> 5;
    const int gwarp = blockIdx.x * (THREADS >> 5) + warp_in_block;
    const int W = WARPS_TOTAL;

    double local = 0.0;

    RowBuf A, B;
    int r = gwarp;

    // Prologue: first row in flight.
    if (r < N) load_row(A, logits, labels, r, C, lane);

    // Unrolled-by-2 ping-pong: next row's loads issue before current consume.
    while (r < N) {
        if (r + W < N) load_row(B, logits, labels, r + W, C, lane);
        consume_row(A, lane, local);                     // row r

        if (r + W < N) {
            if (r + 2 * W < N) load_row(A, logits, labels, r + 2 * W, C, lane);
            consume_row(B, lane, local);                 // row r + W
        }
        r += 2 * W;
    }

    // Block reduction, once per block.
    __shared__ double sh[THREADS >> 5];
    if (lane == 0) sh[warp_in_block] = local;
    __syncthreads();

    if (threadIdx.x == 0) {
        double t = 0.0;
        #pragma unroll
        for (int i = 0; i < (THREADS >> 5); i++) t += sh[i];
        atomicAdd(&g_state.acc, t);

        __threadfence();
        unsigned long long ticket = atomicAdd(&g_state.count, 1ULL);
        if (ticket == (unsigned long long)gridDim.x - 1ULL) {
            double acc = *(volatile double*)&g_state.acc;
            *out = (float)(acc * inv_n);
        }
    }
}

extern "C" void kernel_launch(void* const* d_in, const int* in_sizes, int n_in,
                              void* d_out, int out_size) {
    const float* logits = (const float*)d_in[0];
    const int*   labels = (const int*)d_in[1];
    float* out = (float*)d_out;

    const int N = in_sizes[1];          // rows == labels
    const int C = in_sizes[0] / N;      // 1000

    void* state_ptr = nullptr;
    cudaGetSymbolAddress(&state_ptr, g_state);
    cudaMemsetAsync(state_ptr, 0, sizeof(State), 0);

    cosine_loss_kernel<<<BLOCKS, THREADS>>>(logits, labels, N, C, out,
                                            1.0 / (double)N);
}

// round 10
// speedup vs baseline: 1.0582x; 1.0582x over previous
#include <cuda_runtime.h>
#include <cstdint>

// Zero-initialized at module load; the last-ticket block resets it to zero at
// the end of every call, so no per-call memset node is needed (1-node graph).
struct State { double acc; unsigned long long count; };
__device__ State g_state;   // static init = {0, 0}

static constexpr int BLOCKS  = 444;    // 3 blocks/SM resident (80 regs), persistent
static constexpr int THREADS = 256;    // 8 warps/block
static constexpr int WARPS_TOTAL = BLOCKS * (THREADS / 32);

// R6 winner: software-pipelined persistent warps, snapshot double-buffer.
// Label component extracted from the streamed float4s (no gather load).
__global__ __launch_bounds__(THREADS)
void cosine_loss_kernel(const float* __restrict__ logits,
                        const int* __restrict__ labels,
                        int N, int C, float* __restrict__ out, double inv_n) {
    const int lane  = threadIdx.x & 31;
    const int warp_in_block = threadIdx.x >> 5;
    const int gwarp = blockIdx.x * (THREADS >> 5) + warp_in_block;

    double local = 0.0;

    int row = gwarp;
    float4 v[8];
    int lab = 0;

    // Prologue: loads for the first row.
    if (row < N) {
        const float4* __restrict__ row4 =
            reinterpret_cast<const float4*>(logits + (size_t)row * (size_t)C);
        lab = __ldg(labels + row);
        #pragma unroll
        for (int k = 0; k < 7; k++)
            v[k] = __ldcs(row4 + lane + 32 * k);
        v[7] = make_float4(0.f, 0.f, 0.f, 0.f);
        if (lane < 26)
            v[7] = __ldcs(row4 + lane + 224);
    }

    while (row < N) {
        // Snapshot current row, then issue next row's loads immediately.
        float4 cur[8];
        #pragma unroll
        for (int k = 0; k < 8; k++) cur[k] = v[k];
        const int labc = lab;

        const int next = row + WARPS_TOTAL;
        if (next < N) {
            const float4* __restrict__ row4 =
                reinterpret_cast<const float4*>(logits + (size_t)next * (size_t)C);
            lab = __ldg(labels + next);
            #pragma unroll
            for (int k = 0; k < 7; k++)
                v[k] = __ldcs(row4 + lane + 32 * k);
            v[7] = make_float4(0.f, 0.f, 0.f, 0.f);
            if (lane < 26)
                v[7] = __ldcs(row4 + lane + 224);
        }

        // Reduce current row; extract the label component in-pass.
        const int j4   = labc >> 2;          // float4 index within row [0,250)
        const int comp = labc & 3;
        const int lane_owner = j4 & 31;

        float s = 0.0f;
        float dot_l = 0.0f;
        #pragma unroll
        for (int k = 0; k < 8; k++) {
            if (j4 == lane + 32 * k) {
                dot_l = (comp == 0) ? cur[k].x :
                        (comp == 1) ? cur[k].y :
                        (comp == 2) ? cur[k].z : cur[k].w;
            }
            s = fmaf(cur[k].x, cur[k].x, s);
            s = fmaf(cur[k].y, cur[k].y, s);
            s = fmaf(cur[k].z, cur[k].z, s);
            s = fmaf(cur[k].w, cur[k].w, s);
        }
        #pragma unroll
        for (int o = 16; o > 0; o >>= 1)
            s += __shfl_xor_sync(0xFFFFFFFFu, s, o);
        const float dot = __shfl_sync(0xFFFFFFFFu, dot_l, lane_owner);

        if (lane == 0) {
            const float cosv = dot / fmaxf(sqrtf(s), 1e-8f);
            local += 1.0 - (double)cosv;
        }

        row = next;
    }

    // Block reduction, once per block.
    __shared__ double sh[THREADS >> 5];
    if (lane == 0) sh[warp_in_block] = local;
    __syncthreads();

    if (threadIdx.x == 0) {
        double t = 0.0;
        #pragma unroll
        for (int i = 0; i < (THREADS >> 5); i++) t += sh[i];
        atomicAdd(&g_state.acc, t);

        __threadfence();
        unsigned long long ticket = atomicAdd(&g_state.count, 1ULL);
        if (ticket == (unsigned long long)gridDim.x - 1ULL) {
            // All gridDim.x accumulations are complete (ticket order).
            double acc = *(volatile double*)&g_state.acc;
            *out = (float)(acc * inv_n);
            // Self-reset so the next call starts from a zeroed state:
            // no memset node needed -> 1-node graph.
            g_state.acc = 0.0;
            __threadfence();
            g_state.count = 0ULL;
        }
    }
}

extern "C" void kernel_launch(void* const* d_in, const int* in_sizes, int n_in,
                              void* d_out, int out_size) {
    const float* logits = (const float*)d_in[0];
    const int*   labels = (const int*)d_in[1];
    float* out = (float*)d_out;

    const int N = in_sizes[1];          // rows == labels
    const int C = in_sizes[0] / N;      // 1000

    cosine_loss_kernel<<<BLOCKS, THREADS>>>(logits, labels, N, C, out,
                                            1.0 / (double)N);
}